// round 16
// baseline (speedup 1.0000x reference)
#include <cuda_runtime.h>
#include <math.h>

#define NPIX   (8*256*256)      // 524288 pixels
#define NCH    32
#define NCLASS 8
#define PAIRS  272              // channel-pairs per class (rows padded to even)
#define LFLTS  (PAIRS*2)        // 544 floats per class
#define TPB    128
#define PPT    4
#define PPB    (TPB*PPT)        // 512 pixels per block
#define NBLK   (NPIX/PPB)       // 1024 blocks

// dynamic shared layout (bytes). The 32KB scale stage at offset 0 is dead
// after the post-setup barrier; sG reuses its first 18432 bytes.
#define SC_OFF   0              // staged scale: 32768 B (setup phase only)
#define G_OFF    0              // sG: 18432 B (compute phase, reuses SC)
#define SL_OFF   32768          // sL: 17408 B
#define NW_OFF   (SL_OFF + 17408)        // 50176, 2048 B
#define LOGC_OFF (NW_OFF + 2048)         // 52224, 32 B
#define SM_BYTES (LOGC_OFF + 32)         // 52256

typedef unsigned long long ull;

// ---------- packed f32x2 helpers (sm_103a FFMA2 — PTX only) ----------
__device__ __forceinline__ ull ffma2(ull a, ull b, ull c) {
    ull d;
    asm("fma.rn.f32x2 %0, %1, %2, %3;" : "=l"(d) : "l"(a), "l"(b), "l"(c));
    return d;
}
__device__ __forceinline__ float2 unpack2(ull v) {
    float lo, hi;
    asm("mov.b64 {%0, %1}, %2;" : "=f"(lo), "=f"(hi) : "l"(v));
    return make_float2(lo, hi);
}

// ---------------- single fused kernel: per-block redundant setup ----------------
// Every block independently derives the per-class constants (Linv channel-pair
// rows, -Linv@mean, log-consts) into ITS OWN shared memory (~2.7k cyc critical
// path, overlapped across co-resident blocks), then runs the R12-validated
// compute/epilogue/store path unchanged. No global constant state, no flags,
// no second kernel launch.
__global__ void __launch_bounds__(TPB, 3)
fused_kernel(const float* __restrict__ x,
             const float* __restrict__ mean,
             const float* __restrict__ scale,
             float* __restrict__ out) {
    extern __shared__ __align__(16) char smemRaw[];
    float*  sL    = reinterpret_cast<float*>(smemRaw + SL_OFF);
    float2* sNW   = reinterpret_cast<float2*>(smemRaw + NW_OFF);
    float*  sLogc = reinterpret_cast<float*>(smemRaw + LOGC_OFF);
    float*  sG    = reinterpret_cast<float*>(smemRaw + G_OFF);

    const int tid = threadIdx.x;

    // ================= per-block setup phase =================
    {
        // stage scale (32 KB) into shared with coalesced float4 loads (L2-hot)
        const float4* src = reinterpret_cast<const float4*>(scale);
        float4* dst = reinterpret_cast<float4*>(smemRaw + SC_OFF);
        #pragma unroll
        for (int i = tid; i < NCLASS * NCH * NCH / 4; i += TPB)
            dst[i] = src[i];
    }
    __syncthreads();
    {
        float (*sSc)[NCH][NCH] =
            reinterpret_cast<float (*)[NCH][NCH]>(smemRaw + SC_OFF);
        const int w = tid >> 5;   // warp 0..3
        const int j = tid & 31;   // column / lane

        #pragma unroll
        for (int rep = 0; rep < 2; rep++) {
            const int k = w + rep * 4;    // class

            // lane j: column j of Linv by forward substitution (LDS broadcasts)
            float xcol[NCH];
            #pragma unroll
            for (int i = 0; i < NCH; i++) {
                float s = (i == j) ? 1.0f : 0.0f;
                #pragma unroll
                for (int d = 0; d < i; d++)
                    s -= sSc[k][i][d] * xcol[d];   // tril implied
                xcol[i] = s / sSc[k][i][i];
            }

            // raw channel-pair rows, even-padded — written straight to sL
            int base = 0;
            #pragma unroll
            for (int c = 0; c < NCH; c++) {
                if (j <= c)
                    sL[k * LFLTS + base + j] = xcol[c];   // Linv[c][j]
                if (((c & 1) == 0) && (j == c + 1))
                    sL[k * LFLTS + base + j] = 0.0f;
                base += (c + 2) & ~1;
            }

            // w_i = sum_j Linv[i][j]*mean[j]: butterfly reduce; lane i keeps w_i
            const float mu = mean[k * NCH + j];
            float myw = 0.0f;
            #pragma unroll
            for (int i = 0; i < NCH; i++) {
                float v = xcol[i] * mu;
                #pragma unroll
                for (int m = 16; m > 0; m >>= 1)
                    v += __shfl_xor_sync(0xFFFFFFFFu, v, m);
                if (j == i) myw = v;
            }
            sNW[k * NCH + j] = make_float2(-myw, 0.0f);

            // logdet: lane-parallel logf + butterfly reduce
            float v = logf(fabsf(sSc[k][j][j]));
            #pragma unroll
            for (int m = 16; m > 0; m >>= 1)
                v += __shfl_xor_sync(0xFFFFFFFFu, v, m);
            if (j == 0)
                sLogc[k] = -16.0f * 1.8378770664093453f - v;
        }
    }
    __syncthreads();   // scale reads done (sG may now reuse that region);
                       // sL/sNW/sLogc visible to all warps

    // ================= R12-validated main path =================
    const int pix0 = blockIdx.x * PPB + tid * PPT;

    // ---- load 4 pixels of x as channel-pairs: xp[p][j] = (x[2j], x[2j+1]).
    // Loaded AFTER setup so xcol and xp are never live together (no spills).
    ull xp[PPT][NCH/2];
    {
        const ulonglong2* xg = reinterpret_cast<const ulonglong2*>(x);
        #pragma unroll
        for (int p = 0; p < PPT; p++) {
            const size_t b = (size_t)(pix0 + p) * 8;   // 8 ulonglong2 per pixel
            #pragma unroll
            for (int t = 0; t < 8; t++) {
                ulonglong2 v = xg[b + t];
                xp[p][2*t]   = v.x;
                xp[p][2*t+1] = v.y;
            }
        }
    }

    // ---- per-class triangular whitening with channel-pair FFMA2.
    #pragma unroll 1
    for (int k = 0; k < NCLASS; k++) {
        const ull* Lk  = reinterpret_cast<const ull*>(sL + k * LFLTS);
        const ull* nwk = reinterpret_cast<const ull*>(sNW + k * NCH);
        ull  P0 = 0ULL, P1 = 0ULL, P2 = 0ULL, P3 = 0ULL;
        float c0 = 0.f, c1 = 0.f, c2 = 0.f, c3 = 0.f;
        int off = 0;
        #pragma unroll
        for (int c = 0; c < NCH; c++) {
            const int np = (c + 2) >> 1;      // channel-pairs in this padded row
            ull nv = nwk[c];                  // (-w, 0)
            ull z0 = nv, z1 = nv, z2 = nv, z3 = nv;
            #pragma unroll
            for (int j = 0; j < np; j++) {
                ull lw = Lk[off + j];         // one LDS.64 broadcast -> 4 FFMA2
                z0 = ffma2(xp[0][j], lw, z0);
                z1 = ffma2(xp[1][j], lw, z1);
                z2 = ffma2(xp[2][j], lw, z2);
                z3 = ffma2(xp[3][j], lw, z3);
            }
            off += np;
            float2 u0 = unpack2(z0), u1 = unpack2(z1);
            float2 u2 = unpack2(z2), u3 = unpack2(z3);
            P0 = ffma2(z0, z0, P0);  c0 = fmaf(u0.x, u0.y, c0);
            P1 = ffma2(z1, z1, P1);  c1 = fmaf(u1.x, u1.y, c1);
            P2 = ffma2(z2, z2, P2);  c2 = fmaf(u2.x, u2.y, c2);
            P3 = ffma2(z3, z3, P3);  c3 = fmaf(u3.x, u3.y, c3);
        }
        const float lc = sLogc[k];
        const int base = (tid * PPT) * 9 + k;
        float2 s0 = unpack2(P0), s1 = unpack2(P1);
        float2 s2 = unpack2(P2), s3 = unpack2(P3);
        sG[base     ] = fmaf(-0.5f, s0.x + s0.y, lc - c0);
        sG[base +  9] = fmaf(-0.5f, s1.x + s1.y, lc - c1);
        sG[base + 18] = fmaf(-0.5f, s2.x + s2.y, lc - c2);
        sG[base + 27] = fmaf(-0.5f, s3.x + s3.y, lc - c3);
    }

    // ---- epilogue: log-probs -> l2-normalized (with 1e-12 clamp) gauss weights
    #pragma unroll
    for (int q = 0; q < PPT; q++) {
        const int p = tid * PPT + q;
        float lp[NCLASS];
        #pragma unroll
        for (int k = 0; k < NCLASS; k++) lp[k] = sG[p * 9 + k];
        float m = lp[0];
        #pragma unroll
        for (int k = 1; k < NCLASS; k++) m = fmaxf(m, lp[k]);
        float pr[NCLASS];
        float s = 0.0f;
        #pragma unroll
        for (int k = 0; k < NCLASS; k++) {
            pr[k] = __expf(lp[k] - m);
            s = fmaf(pr[k], pr[k], s);     // s >= 1 always (max term is 1)
        }
        float em = __expf(m);
        float t = em * em * s;             // true sum(prob^2); underflow -> clamp path
        float sc = (t >= 1e-12f) ? rsqrtf(s) : (em * 1.0e6f);
        #pragma unroll
        for (int k = 0; k < NCLASS; k++) sG[p * 9 + k] = pr[k] * sc;
    }
    __syncthreads();

    // ---- store phase: one warp per pixel, fully coalesced 512B STG.128 bursts
    const int lane = tid & 31;
    const int wrp  = tid >> 5;
    const float4* x4 = reinterpret_cast<const float4*>(x);
    float4* o4 = reinterpret_cast<float4*>(out);
    for (int p = wrp; p < PPB; p += TPB / 32) {
        const size_t gp = (size_t)blockIdx.x * PPB + p;
        float4 xv = __ldg(&x4[gp * 8 + (lane & 7)]);        // one 128B line, L1/L2-hot
        float g0 = sG[p * 9 + (lane >> 3)];                 // classes 0..3
        float g1 = sG[p * 9 + 4 + (lane >> 3)];             // classes 4..7
        float4 r0, r1;
        r0.x = xv.x * g0; r0.y = xv.y * g0; r0.z = xv.z * g0; r0.w = xv.w * g0;
        r1.x = xv.x * g1; r1.y = xv.y * g1; r1.z = xv.z * g1; r1.w = xv.w * g1;
        __stcs(&o4[gp * 64 + lane],      r0);               // streaming: don't thrash L2
        __stcs(&o4[gp * 64 + 32 + lane], r1);
    }
}

extern "C" void kernel_launch(void* const* d_in, const int* in_sizes, int n_in,
                              void* d_out, int out_size) {
    const float* x     = (const float*)d_in[0];   // [8,256,256,32]
    const float* mean  = (const float*)d_in[1];   // [8,32]
    const float* scale = (const float*)d_in[2];   // [8,32,32]
    float* out = (float*)d_out;                   // [8,256,256,256]

    cudaFuncSetAttribute(fused_kernel,
                         cudaFuncAttributeMaxDynamicSharedMemorySize, SM_BYTES);
    fused_kernel<<<NBLK, TPB, SM_BYTES>>>(x, mean, scale, out);
}

// round 17
// speedup vs baseline: 1.1724x; 1.1724x over previous
#include <cuda_runtime.h>
#include <math.h>

#define NPIX   (8*256*256)      // 524288 pixels
#define NCH    32
#define NCLASS 8
#define PAIRS  272              // channel-pairs per class (rows padded to even)
#define LFLTS  (PAIRS*2)        // 544 floats per class
#define TPB    128
#define PPT    4
#define PPB    (TPB*PPT)        // 512 pixels per block
#define NBLK   (NPIX/PPB)       // 1024 blocks

typedef unsigned long long ull;

// Precomputed per-class constants (written by setup kernel each launch)
__device__ float  d_Lpair[NCLASS*LFLTS]; // Linv rows, raw channel pairs, even-padded
__device__ float2 d_nw[NCLASS*NCH];      // (-(Linv_k@mean_k)[c], 0)  -> packed z init
__device__ float  d_logc[NCLASS];        // -16*log(2pi) - logdet_k

// ---------- packed f32x2 helpers (sm_103a FFMA2 — PTX only) ----------
__device__ __forceinline__ ull ffma2(ull a, ull b, ull c) {
    ull d;
    asm("fma.rn.f32x2 %0, %1, %2, %3;" : "=l"(d) : "l"(a), "l"(b), "l"(c));
    return d;
}
__device__ __forceinline__ float2 unpack2(ull v) {
    float lo, hi;
    asm("mov.b64 {%0, %1}, %2;" : "=f"(lo), "=f"(hi) : "l"(v));
    return make_float2(lo, hi);
}

// ---------------- setup: latency-optimized (R12) ----------------
// 8 warps, one class each. scale staged to SMEM first (coalesced), so the
// forward-substitution chain runs on LDS broadcasts, not global loads.
__global__ void setup_kernel(const float* __restrict__ mean,
                             const float* __restrict__ scale) {
    __shared__ float sLg[NCLASS][NCH][NCH];   // 32 KB staged scale
    __shared__ float sW[NCLASS][NCH];         // Linv @ mean scratch

    const int tid = threadIdx.x;
    const int k = tid >> 5;   // class (8 warps, 256 threads)
    const int j = tid & 31;   // column / lane

    // coalesced stage: 8192 floats, 2048 float4, 8 per thread
    {
        const float4* src = reinterpret_cast<const float4*>(scale);
        float4* dst = reinterpret_cast<float4*>(&sLg[0][0][0]);
        #pragma unroll
        for (int i = tid; i < NCLASS * NCH * NCH / 4; i += 256)
            dst[i] = src[i];
    }
    __syncthreads();

    // lane j computes column j of Linv by forward substitution (LDS broadcasts)
    float xcol[NCH];
    #pragma unroll
    for (int i = 0; i < NCH; i++) {
        float s = (i == j) ? 1.0f : 0.0f;
        #pragma unroll
        for (int d = 0; d < i; d++)
            s -= sLg[k][i][d] * xcol[d];   // lower triangle only (tril implied)
        xcol[i] = s / sLg[k][i][i];
    }

    // raw channel-pair rows: row c holds L[c,0..c] at float offsets base+d,
    // pad base+c+1 with 0 when c is even. base advances by (c+2)&~1.
    int base = 0;
    #pragma unroll
    for (int c = 0; c < NCH; c++) {
        if (j <= c)
            d_Lpair[k * LFLTS + base + j] = xcol[c];      // L[c, d=j] = Linv[c][j]
        if (((c & 1) == 0) && (j == c + 1))
            d_Lpair[k * LFLTS + base + j] = 0.0f;
        base += (c + 2) & ~1;
    }

    // w_i = sum_j Linv[i][j]*mean[j]: lane-parallel products + butterfly reduce
    const float mu = mean[k * NCH + j];
    #pragma unroll
    for (int i = 0; i < NCH; i++) {
        float v = xcol[i] * mu;
        #pragma unroll
        for (int m = 16; m > 0; m >>= 1)
            v += __shfl_xor_sync(0xFFFFFFFFu, v, m);
        if (j == 0) sW[k][i] = v;
    }
    __syncwarp();
    d_nw[k * NCH + j] = make_float2(-sW[k][j], 0.0f);

    // logdet: lane-parallel logf + butterfly reduce
    {
        float v = logf(fabsf(sLg[k][j][j]));
        #pragma unroll
        for (int m = 16; m > 0; m >>= 1)
            v += __shfl_xor_sync(0xFFFFFFFFu, v, m);
        if (j == 0)
            d_logc[k] = -16.0f * 1.8378770664093453f - v;  // -0.5*32*log(2pi)-logdet
    }
}

// ---------------- main fused kernel (byte-exact R12 core + PDL sync) ----------------
__global__ void __launch_bounds__(TPB, 3)
main_kernel(const float* __restrict__ x, float* __restrict__ out) {
    __shared__ float  sL[NCLASS * LFLTS];   // 17408 B raw pairs
    __shared__ float2 sNW[NCLASS * NCH];    //  2048 B
    __shared__ float  sLogc[NCLASS];        //    32 B
    __shared__ float  sG[PPB * 9];          // 18432 B (stride 9: conflict-light)

    const int tid = threadIdx.x;
    const int pix0 = blockIdx.x * PPB + tid * PPT;

    // ---- PDL prologue: x-tile loads are independent of the setup kernel's
    // output, so issue them BEFORE the grid-dependency wait. The 16 LDG.128
    // (DRAM latency) overlap the upstream setup kernel's drain.
    ull xp[PPT][NCH/2];
    {
        const ulonglong2* xg = reinterpret_cast<const ulonglong2*>(x);
        #pragma unroll
        for (int p = 0; p < PPT; p++) {
            const size_t b = (size_t)(pix0 + p) * 8;   // 8 ulonglong2 per pixel
            #pragma unroll
            for (int t = 0; t < 8; t++) {
                ulonglong2 v = xg[b + t];
                xp[p][2*t]   = v.x;
                xp[p][2*t+1] = v.y;
            }
        }
    }

    // ---- wait for setup kernel completion (PDL hardware dependency)
    cudaGridDependencySynchronize();

    // ---- fill shared constants
    {
        const float4* Ls = reinterpret_cast<const float4*>(d_Lpair);
        float4* Ld = reinterpret_cast<float4*>(sL);
        for (int i = tid; i < NCLASS * LFLTS / 4; i += TPB) Ld[i] = Ls[i];
        for (int i = tid; i < NCLASS * NCH; i += TPB) sNW[i] = d_nw[i];
        if (tid < NCLASS) sLogc[tid] = d_logc[tid];
    }
    __syncthreads();

    // ---- per-class triangular whitening with channel-pair FFMA2.
    #pragma unroll 1
    for (int k = 0; k < NCLASS; k++) {
        const ull* Lk  = reinterpret_cast<const ull*>(sL + k * LFLTS);
        const ull* nwk = reinterpret_cast<const ull*>(sNW + k * NCH);
        ull  P0 = 0ULL, P1 = 0ULL, P2 = 0ULL, P3 = 0ULL;
        float c0 = 0.f, c1 = 0.f, c2 = 0.f, c3 = 0.f;
        int off = 0;
        #pragma unroll
        for (int c = 0; c < NCH; c++) {
            const int np = (c + 2) >> 1;      // channel-pairs in this padded row
            ull nv = nwk[c];                  // (-w, 0)
            ull z0 = nv, z1 = nv, z2 = nv, z3 = nv;
            #pragma unroll
            for (int j = 0; j < np; j++) {
                ull lw = Lk[off + j];         // one LDS.64 broadcast -> 4 FFMA2
                z0 = ffma2(xp[0][j], lw, z0);
                z1 = ffma2(xp[1][j], lw, z1);
                z2 = ffma2(xp[2][j], lw, z2);
                z3 = ffma2(xp[3][j], lw, z3);
            }
            off += np;
            float2 u0 = unpack2(z0), u1 = unpack2(z1);
            float2 u2 = unpack2(z2), u3 = unpack2(z3);
            P0 = ffma2(z0, z0, P0);  c0 = fmaf(u0.x, u0.y, c0);
            P1 = ffma2(z1, z1, P1);  c1 = fmaf(u1.x, u1.y, c1);
            P2 = ffma2(z2, z2, P2);  c2 = fmaf(u2.x, u2.y, c2);
            P3 = ffma2(z3, z3, P3);  c3 = fmaf(u3.x, u3.y, c3);
        }
        const float lc = sLogc[k];
        const int base = (tid * PPT) * 9 + k;
        float2 s0 = unpack2(P0), s1 = unpack2(P1);
        float2 s2 = unpack2(P2), s3 = unpack2(P3);
        sG[base     ] = fmaf(-0.5f, s0.x + s0.y, lc - c0);
        sG[base +  9] = fmaf(-0.5f, s1.x + s1.y, lc - c1);
        sG[base + 18] = fmaf(-0.5f, s2.x + s2.y, lc - c2);
        sG[base + 27] = fmaf(-0.5f, s3.x + s3.y, lc - c3);
    }

    // ---- epilogue: log-probs -> l2-normalized (with 1e-12 clamp) gauss weights
    #pragma unroll
    for (int q = 0; q < PPT; q++) {
        const int p = tid * PPT + q;
        float lp[NCLASS];
        #pragma unroll
        for (int k = 0; k < NCLASS; k++) lp[k] = sG[p * 9 + k];
        float m = lp[0];
        #pragma unroll
        for (int k = 1; k < NCLASS; k++) m = fmaxf(m, lp[k]);
        float pr[NCLASS];
        float s = 0.0f;
        #pragma unroll
        for (int k = 0; k < NCLASS; k++) {
            pr[k] = __expf(lp[k] - m);
            s = fmaf(pr[k], pr[k], s);     // s >= 1 always (max term is 1)
        }
        float em = __expf(m);
        float t = em * em * s;             // true sum(prob^2); underflow -> clamp path
        float sc = (t >= 1e-12f) ? rsqrtf(s) : (em * 1.0e6f);
        #pragma unroll
        for (int k = 0; k < NCLASS; k++) sG[p * 9 + k] = pr[k] * sc;
    }
    __syncthreads();

    // ---- store phase: one warp per pixel, fully coalesced 512B STG.128 bursts
    const int lane = tid & 31;
    const int wrp  = tid >> 5;
    const float4* x4 = reinterpret_cast<const float4*>(x);
    float4* o4 = reinterpret_cast<float4*>(out);
    for (int p = wrp; p < PPB; p += TPB / 32) {
        const size_t gp = (size_t)blockIdx.x * PPB + p;
        float4 xv = __ldg(&x4[gp * 8 + (lane & 7)]);        // one 128B line, L1/L2-hot
        float g0 = sG[p * 9 + (lane >> 3)];                 // classes 0..3
        float g1 = sG[p * 9 + 4 + (lane >> 3)];             // classes 4..7
        float4 r0, r1;
        r0.x = xv.x * g0; r0.y = xv.y * g0; r0.z = xv.z * g0; r0.w = xv.w * g0;
        r1.x = xv.x * g1; r1.y = xv.y * g1; r1.z = xv.z * g1; r1.w = xv.w * g1;
        __stcs(&o4[gp * 64 + lane],      r0);               // streaming: don't thrash L2
        __stcs(&o4[gp * 64 + 32 + lane], r1);
    }
}

extern "C" void kernel_launch(void* const* d_in, const int* in_sizes, int n_in,
                              void* d_out, int out_size) {
    const float* x     = (const float*)d_in[0];   // [8,256,256,32]
    const float* mean  = (const float*)d_in[1];   // [8,32]
    const float* scale = (const float*)d_in[2];   // [8,32,32]
    float* out = (float*)d_out;                   // [8,256,256,256]

    setup_kernel<<<1, 256>>>(mean, scale);

    // PDL launch: main_kernel may be dispatched while setup_kernel drains;
    // each block waits at cudaGridDependencySynchronize() after its x loads.
    cudaLaunchConfig_t cfg = {};
    cfg.gridDim  = dim3(NBLK, 1, 1);
    cfg.blockDim = dim3(TPB, 1, 1);
    cfg.dynamicSmemBytes = 0;
    cfg.stream = 0;
    cudaLaunchAttribute attrs[1];
    attrs[0].id = cudaLaunchAttributeProgrammaticStreamSerialization;
    attrs[0].val.programmaticStreamSerializationAllowed = 1;
    cfg.attrs = attrs;
    cfg.numAttrs = 1;
    cudaError_t e = cudaLaunchKernelEx(&cfg, main_kernel, x, out);
    if (e != cudaSuccess) {
        // fallback: plain serialized launch (identical semantics, R12 behavior)
        main_kernel<<<NBLK, TPB>>>(x, out);
    }
}